// round 9
// baseline (speedup 1.0000x reference)
#include <cuda_runtime.h>

// LNSLinear: the log-number-system formulation is algebraically identical to
// y = x @ W^T + bias in fp32 (sign * 2^(log2|x|+log2|w|) == x*w; the max-
// subtraction is a neutral rescaling). So: plain fp32 tiled GEMM.
//
// Shapes: x [512, 512], weight [512, 512] (N-major, K contiguous), bias [512].
// Output [512, 512] fp32.

#define MDIM 512
#define NDIM 512
#define KDIM 512

#define BM 64
#define BN 32
#define BK 32
// 256 threads: 16 (m) x 16 (n) thread grid, each thread computes 4x2 outputs.

__global__ __launch_bounds__(256, 4)
void lns_linear_gemm(const float* __restrict__ x,
                     const float* __restrict__ w,
                     const float* __restrict__ bias,
                     float* __restrict__ out) {
    __shared__ float As[BK][BM + 4];   // k-major, +4 pad keeps 16B alignment, kills conflicts
    __shared__ float Bs[BK][BN + 4];

    const int t  = threadIdx.x;
    const int bm = blockIdx.y * BM;
    const int bn = blockIdx.x * BN;
    const int tx = t & 15;    // n-direction, 2 outputs each
    const int ty = t >> 4;    // m-direction, 4 outputs each

    float acc[4][2];
#pragma unroll
    for (int i = 0; i < 4; i++) { acc[i][0] = 0.f; acc[i][1] = 0.f; }

    for (int k0 = 0; k0 < KDIM; k0 += BK) {
        // ---- Load A tile: 64 rows x 32 k = 512 float4, 2 per thread ----
#pragma unroll
        for (int i = 0; i < 2; i++) {
            int li  = t + i * 256;
            int row = li >> 3;        // 0..63
            int kq  = li & 7;         // 0..7 (float4 within k-tile)
            float4 v = *(const float4*)(x + (size_t)(bm + row) * KDIM + k0 + kq * 4);
            As[kq * 4 + 0][row] = v.x;
            As[kq * 4 + 1][row] = v.y;
            As[kq * 4 + 2][row] = v.z;
            As[kq * 4 + 3][row] = v.w;
        }
        // ---- Load B (weight) tile: 32 rows x 32 k = 256 float4, 1 per thread ----
        {
            int row = t >> 3;         // 0..31
            int kq  = t & 7;
            float4 v = *(const float4*)(w + (size_t)(bn + row) * KDIM + k0 + kq * 4);
            Bs[kq * 4 + 0][row] = v.x;
            Bs[kq * 4 + 1][row] = v.y;
            Bs[kq * 4 + 2][row] = v.z;
            Bs[kq * 4 + 3][row] = v.w;
        }
        __syncthreads();

        // ---- Compute: 4x2 micro-tile per thread ----
#pragma unroll
        for (int k = 0; k < BK; k++) {
            float4 a = *(const float4*)&As[k][ty * 4];
            float2 b = *(const float2*)&Bs[k][tx * 2];
            acc[0][0] += a.x * b.x;  acc[0][1] += a.x * b.y;
            acc[1][0] += a.y * b.x;  acc[1][1] += a.y * b.y;
            acc[2][0] += a.z * b.x;  acc[2][1] += a.z * b.y;
            acc[3][0] += a.w * b.x;  acc[3][1] += a.w * b.y;
        }
        __syncthreads();
    }

    // ---- Epilogue: add bias, store ----
    const int n0 = bn + tx * 2;
    const float b0 = bias[n0];
    const float b1 = bias[n0 + 1];
#pragma unroll
    for (int im = 0; im < 4; im++) {
        int m = bm + ty * 4 + im;
        float* o = out + (size_t)m * NDIM + n0;
        float2 v;
        v.x = acc[im][0] + b0;
        v.y = acc[im][1] + b1;
        *(float2*)o = v;
    }
}

extern "C" void kernel_launch(void* const* d_in, const int* in_sizes, int n_in,
                              void* d_out, int out_size) {
    const float* x    = (const float*)d_in[0];   // [512, 512]
    const float* w    = (const float*)d_in[1];   // [512, 512]
    const float* bias = (const float*)d_in[2];   // [512]
    float* out        = (float*)d_out;           // [512, 512]

    dim3 grid(NDIM / BN, MDIM / BM);   // (16, 8) = 128 CTAs, ~1 wave on 148 SMs
    lns_linear_gemm<<<grid, 256>>>(x, w, bias, out);
}

// round 10
// speedup vs baseline: 1.0216x; 1.0216x over previous
#include <cuda_runtime.h>

// LNSLinear: the log-number-system formulation is algebraically identical to
// y = x @ W^T + bias in fp32 (sign * 2^(log2|x|+log2|w|) == x*w; the max-
// subtraction is a neutral rescaling). So: plain fp32 tiled GEMM.
//
// Shapes: x [512, 512], weight [512, 512] (N-major, K contiguous), bias [512].
// Output [512, 512] fp32.

#define MDIM 512
#define NDIM 512
#define KDIM 512

#define BM 64
#define BN 32
#define BK 32
// 256 threads: 16 (m) x 16 (n) thread grid, each thread computes 4x2 outputs.

__global__ __launch_bounds__(256, 4)
void lns_linear_gemm(const float* __restrict__ x,
                     const float* __restrict__ w,
                     const float* __restrict__ bias,
                     float* __restrict__ out) {
    __shared__ float As[BK][BM + 4];   // k-major, +4 pad keeps 16B alignment, kills conflicts
    __shared__ float Bs[BK][BN + 4];

    const int t  = threadIdx.x;
    const int bm = blockIdx.y * BM;
    const int bn = blockIdx.x * BN;
    const int tx = t & 15;    // n-direction, 2 outputs each
    const int ty = t >> 4;    // m-direction, 4 outputs each

    float acc[4][2];
#pragma unroll
    for (int i = 0; i < 4; i++) { acc[i][0] = 0.f; acc[i][1] = 0.f; }

    for (int k0 = 0; k0 < KDIM; k0 += BK) {
        // ---- Load A tile: 64 rows x 32 k = 512 float4, 2 per thread ----
#pragma unroll
        for (int i = 0; i < 2; i++) {
            int li  = t + i * 256;
            int row = li >> 3;        // 0..63
            int kq  = li & 7;         // 0..7 (float4 within k-tile)
            float4 v = *(const float4*)(x + (size_t)(bm + row) * KDIM + k0 + kq * 4);
            As[kq * 4 + 0][row] = v.x;
            As[kq * 4 + 1][row] = v.y;
            As[kq * 4 + 2][row] = v.z;
            As[kq * 4 + 3][row] = v.w;
        }
        // ---- Load B (weight) tile: 32 rows x 32 k = 256 float4, 1 per thread ----
        {
            int row = t >> 3;         // 0..31
            int kq  = t & 7;
            float4 v = *(const float4*)(w + (size_t)(bn + row) * KDIM + k0 + kq * 4);
            Bs[kq * 4 + 0][row] = v.x;
            Bs[kq * 4 + 1][row] = v.y;
            Bs[kq * 4 + 2][row] = v.z;
            Bs[kq * 4 + 3][row] = v.w;
        }
        __syncthreads();

        // ---- Compute: 4x2 micro-tile per thread ----
#pragma unroll
        for (int k = 0; k < BK; k++) {
            float4 a = *(const float4*)&As[k][ty * 4];
            float2 b = *(const float2*)&Bs[k][tx * 2];
            acc[0][0] += a.x * b.x;  acc[0][1] += a.x * b.y;
            acc[1][0] += a.y * b.x;  acc[1][1] += a.y * b.y;
            acc[2][0] += a.z * b.x;  acc[2][1] += a.z * b.y;
            acc[3][0] += a.w * b.x;  acc[3][1] += a.w * b.y;
        }
        __syncthreads();
    }

    // ---- Epilogue: add bias, store ----
    const int n0 = bn + tx * 2;
    const float b0 = bias[n0];
    const float b1 = bias[n0 + 1];
#pragma unroll
    for (int im = 0; im < 4; im++) {
        int m = bm + ty * 4 + im;
        float* o = out + (size_t)m * NDIM + n0;
        float2 v;
        v.x = acc[im][0] + b0;
        v.y = acc[im][1] + b1;
        *(float2*)o = v;
    }
}

extern "C" void kernel_launch(void* const* d_in, const int* in_sizes, int n_in,
                              void* d_out, int out_size) {
    const float* x    = (const float*)d_in[0];   // [512, 512]
    const float* w    = (const float*)d_in[1];   // [512, 512]
    const float* bias = (const float*)d_in[2];   // [512]
    float* out        = (float*)d_out;           // [512, 512]

    dim3 grid(NDIM / BN, MDIM / BM);   // (16, 8) = 128 CTAs, ~1 wave on 148 SMs
    lns_linear_gemm<<<grid, 256>>>(x, w, bias, out);
}